// round 13
// baseline (speedup 1.0000x reference)
#include <cuda_runtime.h>
#include <cuda_fp16.h>
#include <cstdint>

#define B_SZ  8
#define C_CH  256
#define N_PIX 4096

typedef unsigned short u16;

// ---------------- scratch (device globals) ----------------
__device__ u16 g_wh[768 * 256],  g_wl[768 * 256];                        // qkv W split
__device__ u16 g_ph[256 * 256],  g_pl[256 * 256];                        // proj W split
__device__ u16 g_xn[B_SZ * N_PIX * C_CH];                                // xn^T [b][n][c] plain
__device__ u16 g_qT[B_SZ * N_PIX * C_CH];                                // q^T plain
__device__ u16 g_kT[B_SZ * N_PIX * C_CH];                                // k^T plain
__device__ u16 g_v [B_SZ * C_CH * N_PIX];                                // v [b][c][m] plain
__device__ u16 g_O [B_SZ * N_PIX * C_CH];                                // O [b][i][c] plain

// ---------------- helpers ----------------
__device__ __forceinline__ uint32_t smem_u32(const void* p) {
    uint32_t a;
    asm("{ .reg .u64 t; cvta.to.shared.u64 t, %1; cvt.u32.u64 %0, t; }" : "=r"(a) : "l"(p));
    return a;
}
__device__ __forceinline__ u16 hbits(float v) {
    return __half_as_ushort(__float2half_rn(v));
}
__device__ __forceinline__ float hval(u16 u) { return __half2float(__ushort_as_half(u)); }
__device__ __forceinline__ uint32_t pk(u16 a, u16 b) { return (uint32_t)a | ((uint32_t)b << 16); }
__device__ __forceinline__ void cpa16(uint32_t dst, const void* src) {
    asm volatile("cp.async.cg.shared.global [%0], [%1], 16;" :: "r"(dst), "l"(src));
}
__device__ __forceinline__ void ldmx4(uint32_t* r, uint32_t addr) {
    asm volatile("ldmatrix.sync.aligned.m8n8.x4.shared.b16 {%0,%1,%2,%3}, [%4];"
                 : "=r"(r[0]), "=r"(r[1]), "=r"(r[2]), "=r"(r[3]) : "r"(addr));
}
__device__ __forceinline__ void mma16816(float* c, const uint32_t* a, const uint32_t* b) {
    asm volatile("mma.sync.aligned.m16n8k16.row.col.f32.f16.f16.f32 "
                 "{%0,%1,%2,%3},{%4,%5,%6,%7},{%8,%9},{%0,%1,%2,%3};"
                 : "+f"(c[0]), "+f"(c[1]), "+f"(c[2]), "+f"(c[3])
                 : "r"(a[0]), "r"(a[1]), "r"(a[2]), "r"(a[3]), "r"(b[0]), "r"(b[1]));
}

#define PIECE 16384
#define SMEM_A2 98304     // QKV/proj GEMM (2 stages * 3 pieces; covers 68096B transpose bounce)
#define SMEM_FA 114688    // fused attn: q 32K + P 16K + 2*32K stages

// ---------------- prep: split weights (fp16) ----------------
__global__ void split_w(const float* __restrict__ qw, const float* __restrict__ pw,
                        u16* qh, u16* ql, u16* ph_, u16* pl_) {
    int i = blockIdx.x * 256 + threadIdx.x;
    if (i < 768 * 256) {
        float v = qw[i];
        u16 h = hbits(v);
        qh[i] = h; ql[i] = hbits(v - hval(h));
    } else {
        int j = i - 768 * 256;
        float v = pw[j];
        u16 h = hbits(v);
        ph_[j] = h; pl_[j] = hbits(v - hval(h));
    }
}

// ---------------- GroupNorm -> plain fp16 transposed xn^T [b][n][c] ----------------
__global__ void __launch_bounds__(256) gn_plain(const float* __restrict__ x,
                                                const float* __restrict__ gw,
                                                const float* __restrict__ gb,
                                                u16* __restrict__ xn) {
    int b = blockIdx.x >> 3, g = blockIdx.x & 7;
    const size_t base = ((size_t)b * C_CH + g * 32) * N_PIX;
    const float* xp = x + base;
    const int TOT = 32 * N_PIX;

    float s = 0.f, s2 = 0.f;
    for (int i = threadIdx.x; i < TOT; i += 256) {
        float v = xp[i]; s += v; s2 += v * v;
    }
    #pragma unroll
    for (int o = 16; o > 0; o >>= 1) {
        s  += __shfl_xor_sync(0xFFFFFFFFu, s,  o);
        s2 += __shfl_xor_sync(0xFFFFFFFFu, s2, o);
    }
    __shared__ float shs[8], shs2[8], s_mean, s_inv, sgw[32], sgb[32];
    int wid = threadIdx.x >> 5, lid = threadIdx.x & 31;
    if (lid == 0) { shs[wid] = s; shs2[wid] = s2; }
    __syncthreads();
    if (threadIdx.x == 0) {
        float ts = 0.f, ts2 = 0.f;
        #pragma unroll
        for (int i = 0; i < 8; i++) { ts += shs[i]; ts2 += shs2[i]; }
        float mean = ts / (float)TOT;
        float var  = ts2 / (float)TOT - mean * mean;
        s_mean = mean; s_inv = rsqrtf(var + 1e-5f);
    }
    if (threadIdx.x < 32) { sgw[threadIdx.x] = gw[g * 32 + threadIdx.x]; sgb[threadIdx.x] = gb[g * 32 + threadIdx.x]; }
    __syncthreads();
    float mean = s_mean, inv = s_inv;

    for (int rep = 0; rep < 16; rep++) {
        int n = threadIdx.x + (rep << 8);
        uint32_t hb[16];
        #pragma unroll
        for (int c2 = 0; c2 < 16; c2++) {
            int c = c2 * 2;
            float v0 = (xp[(size_t)c * N_PIX + n]       - mean) * inv * sgw[c]     + sgb[c];
            float v1 = (xp[(size_t)(c + 1) * N_PIX + n] - mean) * inv * sgw[c + 1] + sgb[c + 1];
            hb[c2] = pk(hbits(v0), hbits(v1));
        }
        size_t di = ((size_t)b * N_PIX + n) * C_CH + g * 32;
        #pragma unroll
        for (int q = 0; q < 4; q++)
            *(uint4*)(xn + di + q * 8) = make_uint4(hb[q*4], hb[q*4+1], hb[q*4+2], hb[q*4+3]);
    }
}

// ---------------- fp16 mma.sync GEMM (QKV / proj only) ----------------
template <int ASPLIT, int EPI>
__global__ void __launch_bounds__(256, 2)
gemm_mma(const u16* __restrict__ Ah, const u16* __restrict__ Al, long long sA, int lda,
         const u16* __restrict__ Bb, long long sB, int ldb,
         int K, int ldc, long long sOut, float alpha,
         const float* __restrict__ bias, const float* __restrict__ resid,
         float* __restrict__ outF,
         u16* __restrict__ o1, u16* __restrict__ o2, u16* __restrict__ o3) {
    extern __shared__ __align__(16) char smem[];
    const int tid = threadIdx.x;
    const int wid = tid >> 5, lane = tid & 31;
    const int wm = wid >> 1, wn = wid & 1;
    const int m0 = blockIdx.y * 128, n0 = blockIdx.x * 128, bz = blockIdx.z;

    const int NSTAGE = ASPLIT ? 2 : 3;
    const int STAGE  = (2 + ASPLIT) * PIECE;
    const int BOFF   = (1 + ASPLIT) * PIECE;

    const u16* Ahb = Ah + sA * bz + (size_t)m0 * lda;
    const u16* Alb = ASPLIT ? (Al + sA * bz + (size_t)m0 * lda) : nullptr;
    const u16* Bpb = Bb + sB * bz + (size_t)n0 * ldb;

    const uint32_t sb = smem_u32(smem);
    float acc[2][8][4] = {};

    uint32_t dstOff[4];
    uint32_t gOffA[4], gOffB[4];
    #pragma unroll
    for (int it = 0; it < 4; it++) {
        int id = tid + (it << 8);
        int row = id >> 3, kc = id & 7;
        dstOff[it] = (uint32_t)(row << 7) + (uint32_t)((kc << 4) ^ ((row & 7) << 4));
        gOffA[it] = (uint32_t)(row * lda + kc * 8);
        gOffB[it] = (uint32_t)(row * ldb + kc * 8);
    }

    const int ar  = lane & 15;
    const int akb = (lane >> 4) << 4;
    const int br  = (lane & 7) + ((lane >> 4) << 3);
    const int bkb = ((lane >> 3) & 1) << 4;
    uint32_t aOff[2][4], bOff[4][4];
    #pragma unroll
    for (int mt = 0; mt < 2; mt++) {
        int r = wm * 32 + mt * 16 + ar;
        #pragma unroll
        for (int ks = 0; ks < 4; ks++)
            aOff[mt][ks] = (uint32_t)(r << 7) + (uint32_t)(((ks << 5) + akb) ^ ((r & 7) << 4));
    }
    #pragma unroll
    for (int nt2 = 0; nt2 < 4; nt2++) {
        int r = wn * 64 + nt2 * 16 + br;
        #pragma unroll
        for (int ks = 0; ks < 4; ks++)
            bOff[nt2][ks] = (uint32_t)BOFF + (uint32_t)(r << 7) + (uint32_t)(((ks << 5) + bkb) ^ ((r & 7) << 4));
    }

    const int NC = K >> 6;
    #pragma unroll
    for (int s = 0; s < 2; s++) {
        if (s < NSTAGE - 1) {
            uint32_t stB = sb + s * STAGE;
            int k0 = s << 6;
            #pragma unroll
            for (int it = 0; it < 4; it++) {
                cpa16(stB + dstOff[it], Ahb + k0 + gOffA[it]);
                if (ASPLIT) cpa16(stB + PIECE + dstOff[it], Alb + k0 + gOffA[it]);
                cpa16(stB + BOFF + dstOff[it], Bpb + k0 + gOffB[it]);
            }
            asm volatile("cp.async.commit_group;" ::: "memory");
        }
    }

    for (int c = 0; c < NC; c++) {
        if (ASPLIT) asm volatile("cp.async.wait_group 0;" ::: "memory");
        else        asm volatile("cp.async.wait_group 1;" ::: "memory");
        __syncthreads();
        int pf = c + NSTAGE - 1;
        if (pf < NC) {
            uint32_t stB = sb + (pf % NSTAGE) * STAGE;
            int k0 = pf << 6;
            #pragma unroll
            for (int it = 0; it < 4; it++) {
                cpa16(stB + dstOff[it], Ahb + k0 + gOffA[it]);
                if (ASPLIT) cpa16(stB + PIECE + dstOff[it], Alb + k0 + gOffA[it]);
                cpa16(stB + BOFF + dstOff[it], Bpb + k0 + gOffB[it]);
            }
        }
        asm volatile("cp.async.commit_group;" ::: "memory");

        uint32_t st = sb + (c % NSTAGE) * STAGE;
        #pragma unroll
        for (int ks = 0; ks < 4; ks++) {
            uint32_t a_h[2][4], a_l[2][4];
            #pragma unroll
            for (int mt = 0; mt < 2; mt++) {
                ldmx4(a_h[mt], st + aOff[mt][ks]);
                if (ASPLIT) ldmx4(a_l[mt], st + PIECE + aOff[mt][ks]);
            }
            #pragma unroll
            for (int nt2 = 0; nt2 < 4; nt2++) {
                uint32_t b_f[4];
                ldmx4(b_f, st + bOff[nt2][ks]);
                #pragma unroll
                for (int mt = 0; mt < 2; mt++) {
                    mma16816(acc[mt][nt2 * 2],     a_h[mt], b_f);
                    mma16816(acc[mt][nt2 * 2 + 1], a_h[mt], b_f + 2);
                }
                if (ASPLIT) {
                    #pragma unroll
                    for (int mt = 0; mt < 2; mt++) {
                        mma16816(acc[mt][nt2 * 2],     a_l[mt], b_f);
                        mma16816(acc[mt][nt2 * 2 + 1], a_l[mt], b_f + 2);
                    }
                }
            }
        }
    }

    const int rB = lane >> 2;
    const int cB = (lane & 3) * 2;

    if (EPI == 3) {
        float* Ob = outF + sOut * bz;
        const float* Rb = resid + sOut * bz;
        #pragma unroll
        for (int mt = 0; mt < 2; mt++)
            #pragma unroll
            for (int nt = 0; nt < 8; nt++)
                #pragma unroll
                for (int h = 0; h < 2; h++) {
                    int rowG = m0 + wm * 32 + mt * 16 + rB + h * 8;
                    int colG = n0 + wn * 64 + nt * 8 + cB;
                    float bv = bias[rowG];
                    size_t di = (size_t)rowG * ldc + colG;
                    float2 rv = *(const float2*)(Rb + di);
                    float2 v = make_float2(acc[mt][nt][h * 2] + bv + rv.x,
                                           acc[mt][nt][h * 2 + 1] + bv + rv.y);
                    *(float2*)(Ob + di) = v;
                }
    } else {  // EPI 2: qkv
        int sect = m0 >> 8;
        int msub = m0 & 255;
        if (sect == 2) {   // v: plain store [c][4096] + bias
            u16* V = o3 + (size_t)1048576 * bz;
            #pragma unroll
            for (int mt = 0; mt < 2; mt++)
                #pragma unroll
                for (int nt = 0; nt < 8; nt++)
                    #pragma unroll
                    for (int h = 0; h < 2; h++) {
                        int rowL = wm * 32 + mt * 16 + rB + h * 8;
                        float bv = bias[m0 + rowL];
                        int colG = n0 + wn * 64 + nt * 8 + cB;
                        *(uint32_t*)(V + (size_t)(msub + rowL) * N_PIX + colG) =
                            pk(hbits(acc[mt][nt][h * 2] + bv), hbits(acc[mt][nt][h * 2 + 1] + bv));
                    }
        } else {           // q/k: transpose via SMEM bounce -> plain [n][256]
            u16* D = (sect ? o2 : o1) + (size_t)1048576 * bz;
            float* tsm = (float*)smem;
            __syncthreads();
            #pragma unroll
            for (int mt = 0; mt < 2; mt++)
                #pragma unroll
                for (int h = 0; h < 2; h++) {
                    int rowL = wm * 32 + mt * 16 + rB + h * 8;
                    float bv = bias[m0 + rowL];
                    #pragma unroll
                    for (int nt = 0; nt < 8; nt++) {
                        int colL = wn * 64 + nt * 8 + cB;
                        tsm[rowL * 133 + colL]     = acc[mt][nt][h * 2] + bv;
                        tsm[rowL * 133 + colL + 1] = acc[mt][nt][h * 2 + 1] + bv;
                    }
                }
            __syncthreads();
            #pragma unroll
            for (int it = 0; it < 32; it++) {
                int lin = tid + (it << 8);
                int n  = lin >> 6;
                int op = (lin & 63) << 1;
                float f0 = tsm[op * 133 + n];
                float f1 = tsm[(op + 1) * 133 + n];
                *(uint32_t*)(D + (size_t)(n0 + n) * C_CH + msub + op) = pk(hbits(f0), hbits(f1));
            }
        }
    }
}

// ---------------- fused attention: QK^T -> exp -> P@V, one i-tile (64) per CTA ----------------
__device__ __forceinline__ void qk_step(uint32_t qp, uint32_t kp,
                                        float (*acc_s)[4],
                                        const uint32_t* aOff,
                                        const uint32_t (*kOff)[4]) {
    #pragma unroll
    for (int ks = 0; ks < 4; ks++) {
        uint32_t aq[4], b0[4], b1[4];
        ldmx4(aq, qp + aOff[ks]);
        ldmx4(b0, kp + kOff[0][ks]);
        ldmx4(b1, kp + kOff[1][ks]);
        mma16816(acc_s[0], aq, b0); mma16816(acc_s[1], aq, b0 + 2);
        mma16816(acc_s[2], aq, b1); mma16816(acc_s[3], aq, b1 + 2);
    }
}
__device__ __forceinline__ void av_step(uint32_t pp, uint32_t vp,
                                        float (*acc_o)[4],
                                        const uint32_t* aOff,
                                        const uint32_t (*vOff)[4]) {
    #pragma unroll
    for (int ks = 0; ks < 4; ks++) {
        uint32_t ap[4];
        ldmx4(ap, pp + aOff[ks]);
        #pragma unroll
        for (int nt2 = 0; nt2 < 4; nt2++) {
            uint32_t bv[4];
            ldmx4(bv, vp + vOff[nt2][ks]);
            mma16816(acc_o[nt2 * 2],     ap, bv);
            mma16816(acc_o[nt2 * 2 + 1], ap, bv + 2);
        }
    }
}

__global__ void __launch_bounds__(512, 1)
fused_attn(const u16* __restrict__ qT, const u16* __restrict__ kT,
           const u16* __restrict__ vv, u16* __restrict__ O) {
    extern __shared__ __align__(16) char smem[];
    const int tid = threadIdx.x;
    const int wid = tid >> 5, lane = tid & 31;
    const int wm = wid >> 2, wn = wid & 3;     // 4x4 warps
    const int i0 = blockIdx.x * 64;
    const int bz = blockIdx.y;

    const u16* qB = qT + (size_t)bz * N_PIX * C_CH + (size_t)i0 * C_CH;
    const u16* kB = kT + (size_t)bz * N_PIX * C_CH;
    const u16* vB = vv + (size_t)bz * C_CH * N_PIX;
    u16* OB = g_O + 0;  // placeholder (avoid unused warning path)
    OB = O + (size_t)bz * N_PIX * C_CH + (size_t)i0 * C_CH;

    const uint32_t sb   = smem_u32(smem);
    const uint32_t qb   = sb;             // 4 pieces [64][128B] = 32KB
    const uint32_t Pb   = sb + 32768;     // 2 pieces [64][128B] = 16KB
    const uint32_t bufA = sb + 49152;     // 32KB stage
    const uint32_t bufB = sb + 81920;     // 32KB stage

    // ---- loader offsets ----
    uint32_t qDst[4], kDst[4], vDst[4], qSrc[4], kSrc[4], vSrc[4];
    #pragma unroll
    for (int it = 0; it < 4; it++) {
        int id = tid + (it << 9);
        { int pc = id >> 9, row = (id >> 3) & 63, kc = id & 7;
          qDst[it] = (uint32_t)(pc * 8192 + (row << 7) + ((kc << 4) ^ ((row & 7) << 4)));
          qSrc[it] = (uint32_t)(row * C_CH + pc * 64 + kc * 8); }
        { int pc = id >> 10, row = (id >> 3) & 127, kc = id & 7;
          kDst[it] = (uint32_t)(pc * 16384 + (row << 7) + ((kc << 4) ^ ((row & 7) << 4)));
          kSrc[it] = (uint32_t)(row * C_CH + pc * 64 + kc * 8); }
        { int row = (id >> 3) & 255, kc = id & 7;
          vDst[it] = (uint32_t)((row << 7) + ((kc << 4) ^ ((row & 7) << 4)));
          vSrc[it] = (uint32_t)(row * N_PIX + kc * 8); }
    }

    // ---- ldmatrix offsets ----
    const int ar  = lane & 15;
    const int akb = (lane >> 4) << 4;
    const int br  = (lane & 7) + ((lane >> 4) << 3);
    const int bkb = ((lane >> 3) & 1) << 4;
    uint32_t aOff[4];
    { int r = wm * 16 + ar;
      #pragma unroll
      for (int ks = 0; ks < 4; ks++)
          aOff[ks] = (uint32_t)(r << 7) + (uint32_t)(((ks << 5) + akb) ^ ((r & 7) << 4)); }
    uint32_t kOff[2][4];
    #pragma unroll
    for (int nt2 = 0; nt2 < 2; nt2++) {
        int r = wn * 32 + nt2 * 16 + br;
        #pragma unroll
        for (int ks = 0; ks < 4; ks++)
            kOff[nt2][ks] = (uint32_t)(r << 7) + (uint32_t)(((ks << 5) + bkb) ^ ((r & 7) << 4));
    }
    uint32_t vOff[4][4];
    #pragma unroll
    for (int nt2 = 0; nt2 < 4; nt2++) {
        int r = wn * 64 + nt2 * 16 + br;
        #pragma unroll
        for (int ks = 0; ks < 4; ks++)
            vOff[nt2][ks] = (uint32_t)(r << 7) + (uint32_t)(((ks << 5) + bkb) ^ ((r & 7) << 4));
    }
    // P write offsets
    const int rB = lane >> 2, cB = (lane & 3) * 2;
    uint32_t pw[4][2];
    #pragma unroll
    for (int nt = 0; nt < 4; nt++)
        #pragma unroll
        for (int h = 0; h < 2; h++) {
            int row = wm * 16 + rB + h * 8;
            int cn  = wn * 32 + nt * 8 + cB;
            pw[nt][h] = Pb + (uint32_t)((cn >> 6) * 8192 + (row << 7) + (((cn & 63) * 2) ^ ((row & 7) << 4)));
        }

    float acc_o[8][4] = {};
    float rs0 = 0.f, rs1 = 0.f;

    // ---- prologue loads: q, kp0(jt0), kp1(jt0) ----
    #pragma unroll
    for (int it = 0; it < 4; it++) cpa16(qb + qDst[it], qB + qSrc[it]);
    asm volatile("cp.async.commit_group;" ::: "memory");
    #pragma unroll
    for (int it = 0; it < 4; it++) cpa16(bufA + kDst[it], kB + kSrc[it]);
    asm volatile("cp.async.commit_group;" ::: "memory");
    #pragma unroll
    for (int it = 0; it < 4; it++) cpa16(bufB + kDst[it], kB + kSrc[it] + 128);
    asm volatile("cp.async.commit_group;" ::: "memory");

    for (int jt = 0; jt < 32; jt++) {
        const u16* vJ = vB + jt * 128;
        const u16* kN = kB + (size_t)(jt + 1) * 128 * C_CH;
        float acc_s[4][4] = {};

        // QK kc0,kc1 (bufA)
        asm volatile("cp.async.wait_group 1;" ::: "memory");
        __syncthreads();
        qk_step(qb,        bufA,         acc_s, aOff, kOff);
        qk_step(qb + 8192, bufA + 16384, acc_s, aOff, kOff);
        __syncthreads();
        #pragma unroll
        for (int it = 0; it < 4; it++) cpa16(bufA + vDst[it], vJ + vSrc[it]);
        asm volatile("cp.async.commit_group;" ::: "memory");
        asm volatile("cp.async.wait_group 1;" ::: "memory");
        __syncthreads();
        // QK kc2,kc3 (bufB)
        qk_step(qb + 16384, bufB,         acc_s, aOff, kOff);
        qk_step(qb + 24576, bufB + 16384, acc_s, aOff, kOff);
        // exp -> P smem + rowsum partials
        #pragma unroll
        for (int nt = 0; nt < 4; nt++) {
            float e0 = __expf(acc_s[nt][0] * 0.0625f);
            float e1 = __expf(acc_s[nt][1] * 0.0625f);
            float e2 = __expf(acc_s[nt][2] * 0.0625f);
            float e3 = __expf(acc_s[nt][3] * 0.0625f);
            rs0 += e0 + e1; rs1 += e2 + e3;
            uint32_t v01 = pk(hbits(e0), hbits(e1));
            uint32_t v23 = pk(hbits(e2), hbits(e3));
            asm volatile("st.shared.b32 [%0], %1;" :: "r"(pw[nt][0]), "r"(v01) : "memory");
            asm volatile("st.shared.b32 [%0], %1;" :: "r"(pw[nt][1]), "r"(v23) : "memory");
        }
        __syncthreads();
        #pragma unroll
        for (int it = 0; it < 4; it++) cpa16(bufB + vDst[it], vJ + 64 + vSrc[it]);
        asm volatile("cp.async.commit_group;" ::: "memory");
        asm volatile("cp.async.wait_group 1;" ::: "memory");
        __syncthreads();
        // AV mc0 (P piece0, v in bufA)
        av_step(Pb, bufA, acc_o, aOff, vOff);
        __syncthreads();
        if (jt + 1 < 32) {
            #pragma unroll
            for (int it = 0; it < 4; it++) cpa16(bufA + kDst[it], kN + kSrc[it]);
        }
        asm volatile("cp.async.commit_group;" ::: "memory");
        asm volatile("cp.async.wait_group 1;" ::: "memory");
        __syncthreads();
        // AV mc1 (P piece1, v in bufB)
        av_step(Pb + 8192, bufB, acc_o, aOff, vOff);
        __syncthreads();
        if (jt + 1 < 32) {
            #pragma unroll
            for (int it = 0; it < 4; it++) cpa16(bufB + kDst[it], kN + kSrc[it] + 128);
        }
        asm volatile("cp.async.commit_group;" ::: "memory");
    }

    // ---- rowsum finalize + scale + store O ----
    rs0 += __shfl_xor_sync(0xFFFFFFFFu, rs0, 1);
    rs0 += __shfl_xor_sync(0xFFFFFFFFu, rs0, 2);
    rs1 += __shfl_xor_sync(0xFFFFFFFFu, rs1, 1);
    rs1 += __shfl_xor_sync(0xFFFFFFFFu, rs1, 2);
    float* rsm = (float*)smem;   // reuse q area (q no longer read)
    if ((lane & 3) == 0) {
        rsm[wn * 64 + wm * 16 + rB]     = rs0;
        rsm[wn * 64 + wm * 16 + rB + 8] = rs1;
    }
    __syncthreads();
    int row0 = wm * 16 + rB, row1 = row0 + 8;
    float inv0 = 1.0f / (rsm[row0] + rsm[64 + row0] + rsm[128 + row0] + rsm[192 + row0]);
    float inv1 = 1.0f / (rsm[row1] + rsm[64 + row1] + rsm[128 + row1] + rsm[192 + row1]);
    #pragma unroll
    for (int nt = 0; nt < 8; nt++) {
        int col = wn * 64 + nt * 8 + cB;
        *(uint32_t*)(OB + (size_t)row0 * C_CH + col) =
            pk(hbits(acc_o[nt][0] * inv0), hbits(acc_o[nt][1] * inv0));
        *(uint32_t*)(OB + (size_t)row1 * C_CH + col) =
            pk(hbits(acc_o[nt][2] * inv1), hbits(acc_o[nt][3] * inv1));
    }
}

// ---------------- launch ----------------
extern "C" void kernel_launch(void* const* d_in, const int* in_sizes, int n_in,
                              void* d_out, int out_size) {
    const float* x      = (const float*)d_in[0];
    const float* gn_w   = (const float*)d_in[1];
    const float* gn_b   = (const float*)d_in[2];
    const float* qkv_w  = (const float*)d_in[3];
    const float* qkv_b  = (const float*)d_in[4];
    const float* proj_w = (const float*)d_in[5];
    const float* proj_b = (const float*)d_in[6];
    float* out = (float*)d_out;

    u16 *wh, *wl, *ph, *pl, *xn, *qT, *kT, *v, *O;
    cudaGetSymbolAddress((void**)&wh, g_wh);   cudaGetSymbolAddress((void**)&wl, g_wl);
    cudaGetSymbolAddress((void**)&ph, g_ph);   cudaGetSymbolAddress((void**)&pl, g_pl);
    cudaGetSymbolAddress((void**)&xn, g_xn);
    cudaGetSymbolAddress((void**)&qT, g_qT);   cudaGetSymbolAddress((void**)&kT, g_kT);
    cudaGetSymbolAddress((void**)&v, g_v);     cudaGetSymbolAddress((void**)&O, g_O);

    cudaFuncSetAttribute((const void*)gemm_mma<1, 2>, cudaFuncAttributeMaxDynamicSharedMemorySize, SMEM_A2);
    cudaFuncSetAttribute((const void*)gemm_mma<1, 3>, cudaFuncAttributeMaxDynamicSharedMemorySize, SMEM_A2);
    cudaFuncSetAttribute((const void*)fused_attn, cudaFuncAttributeMaxDynamicSharedMemorySize, SMEM_FA);

    const long long sNC = (long long)N_PIX * C_CH;      // 1M

    // 0) split weights
    split_w<<<1024, 256>>>(qkv_w, proj_w, wh, wl, ph, pl);

    // 1) GroupNorm -> xn^T plain fp16
    gn_plain<<<64, 256>>>(x, gn_w, gn_b, xn);

    // 2) QKV (A=W split, B=xn plain): -> q/k plain T, v plain
    gemm_mma<1, 2><<<dim3(32, 6, B_SZ), 256, SMEM_A2>>>(
        wh, wl, 0, C_CH, xn, sNC, C_CH, C_CH, 0, 0, 1.0f,
        qkv_b, nullptr, nullptr, qT, kT, v);

    // 3) fused attention: O[i][c] = softmax(q k^T / 16) v
    fused_attn<<<dim3(64, B_SZ), 512, SMEM_FA>>>(qT, kT, v, O);

    // 4) proj (A=P split, B=O plain): out[o,i] = sum_c Pw[o,c] O[i,c] + pb[o] + x
    gemm_mma<1, 3><<<dim3(32, 2, B_SZ), 256, SMEM_A2>>>(
        ph, pl, 0, C_CH, O, sNC, C_CH, C_CH, N_PIX, sNC, 1.0f,
        proj_b, x, out, nullptr, nullptr, nullptr);
}

// round 14
// speedup vs baseline: 1.2675x; 1.2675x over previous
#include <cuda_runtime.h>
#include <cuda_fp16.h>
#include <cstdint>

#define B_SZ  8
#define C_CH  256
#define N_PIX 4096

typedef unsigned short u16;

// ---------------- scratch (device globals) ----------------
__device__ u16 g_w[768 * 256];                                           // qkv W plain fp16
__device__ u16 g_p[256 * 256];                                           // proj W plain fp16
__device__ u16 g_xn[B_SZ * N_PIX * C_CH];                                // xn^T [b][n][c] plain
__device__ u16 g_qT[B_SZ * N_PIX * C_CH];                                // q^T plain
__device__ u16 g_kT[B_SZ * N_PIX * C_CH];                                // k^T plain
__device__ u16 g_v [B_SZ * C_CH * N_PIX];                                // v [b][c][m] plain
__device__ u16 g_P [(size_t)B_SZ * N_PIX * N_PIX];                       // P~ plain (256MB)
__device__ float g_part[(size_t)B_SZ * N_PIX * 64];                      // row partial sums
__device__ float g_rsum[B_SZ * N_PIX];                                   // reciprocal row sums
__device__ float2 g_gnp[64 * 8];                                         // gn partial sums
__device__ u16 g_O [B_SZ * N_PIX * C_CH];                                // O [b][i][c] plain

// ---------------- helpers ----------------
__device__ __forceinline__ uint32_t smem_u32(const void* p) {
    uint32_t a;
    asm("{ .reg .u64 t; cvta.to.shared.u64 t, %1; cvt.u32.u64 %0, t; }" : "=r"(a) : "l"(p));
    return a;
}
__device__ __forceinline__ u16 hbits(float v) {
    return __half_as_ushort(__float2half_rn(v));
}
__device__ __forceinline__ uint32_t pk(u16 a, u16 b) { return (uint32_t)a | ((uint32_t)b << 16); }
__device__ __forceinline__ void cpa16(uint32_t dst, const void* src) {
    asm volatile("cp.async.cg.shared.global [%0], [%1], 16;" :: "r"(dst), "l"(src));
}
__device__ __forceinline__ void ldmx4(uint32_t* r, uint32_t addr) {
    asm volatile("ldmatrix.sync.aligned.m8n8.x4.shared.b16 {%0,%1,%2,%3}, [%4];"
                 : "=r"(r[0]), "=r"(r[1]), "=r"(r[2]), "=r"(r[3]) : "r"(addr));
}
__device__ __forceinline__ void mma16816(float* c, const uint32_t* a, const uint32_t* b) {
    asm volatile("mma.sync.aligned.m16n8k16.row.col.f32.f16.f16.f32 "
                 "{%0,%1,%2,%3},{%4,%5,%6,%7},{%8,%9},{%0,%1,%2,%3};"
                 : "+f"(c[0]), "+f"(c[1]), "+f"(c[2]), "+f"(c[3])
                 : "r"(a[0]), "r"(a[1]), "r"(a[2]), "r"(a[3]), "r"(b[0]), "r"(b[1]));
}

// K-chunk = 64: piece = 128 rows x 128B (swizzled), 16KB
#define PIECE 16384
#define SMEM_A1 98304   // 3 stages * 2 pieces (also covers 68096B transpose bounce)

// ---------------- prep: convert weights to plain fp16 ----------------
__global__ void conv_w(const float* __restrict__ qw, const float* __restrict__ pw,
                       u16* q_, u16* p_) {
    int i = blockIdx.x * 256 + threadIdx.x;
    if (i < 768 * 256) q_[i] = hbits(qw[i]);
    else               p_[i - 768 * 256] = hbits(pw[i - 768 * 256]);
}

// ---------------- GroupNorm stats: 512 blocks, partial sums ----------------
__global__ void __launch_bounds__(256) gn_stats(const float* __restrict__ x,
                                                float2* __restrict__ part) {
    int bg = blockIdx.x, sl = blockIdx.y;   // 64 x 8
    const float* xp = x + (size_t)bg * 131072 + (size_t)sl * 16384;
    float s = 0.f, s2 = 0.f;
    #pragma unroll 4
    for (int i = threadIdx.x; i < 16384; i += 256) {
        float v = xp[i]; s += v; s2 += v * v;
    }
    #pragma unroll
    for (int o = 16; o > 0; o >>= 1) {
        s  += __shfl_xor_sync(0xFFFFFFFFu, s,  o);
        s2 += __shfl_xor_sync(0xFFFFFFFFu, s2, o);
    }
    __shared__ float shs[8], shs2[8];
    int wid = threadIdx.x >> 5, lid = threadIdx.x & 31;
    if (lid == 0) { shs[wid] = s; shs2[wid] = s2; }
    __syncthreads();
    if (threadIdx.x == 0) {
        float ts = 0.f, ts2 = 0.f;
        #pragma unroll
        for (int i = 0; i < 8; i++) { ts += shs[i]; ts2 += shs2[i]; }
        part[bg * 8 + sl] = make_float2(ts, ts2);
    }
}

// ---------------- GroupNorm apply: normalize + fp16 + transpose write ----------------
__global__ void __launch_bounds__(256) gn_apply(const float* __restrict__ x,
                                                const float* __restrict__ gw,
                                                const float* __restrict__ gb,
                                                const float2* __restrict__ part,
                                                u16* __restrict__ xn) {
    int bg = blockIdx.x, sl = blockIdx.y;   // 64 x 8 (sl = 4-channel slice)
    int b = bg >> 3, g = bg & 7;
    float ts = 0.f, ts2 = 0.f;
    #pragma unroll
    for (int i = 0; i < 8; i++) {
        float2 p = part[bg * 8 + i];
        ts += p.x; ts2 += p.y;
    }
    const float mean = ts * (1.0f / 131072.0f);
    const float inv  = rsqrtf(ts2 * (1.0f / 131072.0f) - mean * mean + 1e-5f);

    int cbase = g * 32 + sl * 4;
    float w0 = gw[cbase] * inv,     b0 = gb[cbase];
    float w1 = gw[cbase + 1] * inv, b1 = gb[cbase + 1];
    float w2 = gw[cbase + 2] * inv, b2 = gb[cbase + 2];
    float w3 = gw[cbase + 3] * inv, b3 = gb[cbase + 3];

    const float* xp = x + ((size_t)(b * 256 + cbase)) * N_PIX;
    u16* dst = xn + (size_t)b * N_PIX * C_CH + cbase;
    #pragma unroll
    for (int rep = 0; rep < 16; rep++) {
        int n = threadIdx.x + (rep << 8);
        float v0 = (xp[n]                 - mean) * w0 + b0;
        float v1 = (xp[n + N_PIX]         - mean) * w1 + b1;
        float v2 = (xp[n + 2 * N_PIX]     - mean) * w2 + b2;
        float v3 = (xp[n + 3 * N_PIX]     - mean) * w3 + b3;
        *(uint2*)(dst + (size_t)n * C_CH) = make_uint2(pk(hbits(v0), hbits(v1)),
                                                       pk(hbits(v2), hbits(v3)));
    }
}

// ---------------- rowsum reduce ----------------
__global__ void __launch_bounds__(256) rowsum_reduce(const float* __restrict__ part,
                                                     float* __restrict__ rsum) {
    int gw = (blockIdx.x * 256 + threadIdx.x) >> 5;
    int lane = threadIdx.x & 31;
    const float* p = part + (size_t)gw * 64;
    float s = p[lane] + p[lane + 32];
    #pragma unroll
    for (int o = 16; o > 0; o >>= 1) s += __shfl_xor_sync(0xFFFFFFFFu, s, o);
    if (lane == 0) rsum[gw] = 1.0f / s;
}

// ---------------- fp16 mma.sync GEMM ----------------
// D[m,n] = sum_k A(m,k)*B(n,k); 128x128 tile; k-major; A and B plain fp16, 3-stage pipeline.
// EPI: 0 scores (exp(alpha*S) -> plain P + partial sums), 1 AV (scale by rsum, plain store),
//      2 qkv (bias; q/k transposed plain, v plain), 3 proj (bias + resid, fp32)
template <int EPI>
__global__ void __launch_bounds__(256, 2)
gemm_mma(const u16* __restrict__ Ab, long long sA, int lda,
         const u16* __restrict__ Bb, long long sB, int ldb,
         int K, int ldc, long long sOut, float alpha,
         const float* __restrict__ bias, const float* __restrict__ resid,
         float* __restrict__ outF,
         u16* __restrict__ o1, u16* __restrict__ o2, u16* __restrict__ o3) {
    extern __shared__ __align__(16) char smem[];
    const int tid = threadIdx.x;
    const int wid = tid >> 5, lane = tid & 31;
    const int wm = wid >> 1, wn = wid & 1;
    const int m0 = blockIdx.y * 128, n0 = blockIdx.x * 128, bz = blockIdx.z;

    const int NSTAGE = 3;
    const int STAGE  = 2 * PIECE;
    const int BOFF   = PIECE;

    const u16* Ahb = Ab + sA * bz + (size_t)m0 * lda;
    const u16* Bpb = Bb + sB * bz + (size_t)n0 * ldb;

    const uint32_t sb = smem_u32(smem);
    float acc[2][8][4] = {};

    uint32_t dstOff[4];
    uint32_t gOffA[4], gOffB[4];
    #pragma unroll
    for (int it = 0; it < 4; it++) {
        int id = tid + (it << 8);
        int row = id >> 3, kc = id & 7;
        dstOff[it] = (uint32_t)(row << 7) + (uint32_t)((kc << 4) ^ ((row & 7) << 4));
        gOffA[it] = (uint32_t)(row * lda + kc * 8);
        gOffB[it] = (uint32_t)(row * ldb + kc * 8);
    }

    const int ar  = lane & 15;
    const int akb = (lane >> 4) << 4;
    const int br  = (lane & 7) + ((lane >> 4) << 3);
    const int bkb = ((lane >> 3) & 1) << 4;
    uint32_t aOff[2][4], bOff[4][4];
    #pragma unroll
    for (int mt = 0; mt < 2; mt++) {
        int r = wm * 32 + mt * 16 + ar;
        #pragma unroll
        for (int ks = 0; ks < 4; ks++)
            aOff[mt][ks] = (uint32_t)(r << 7) + (uint32_t)(((ks << 5) + akb) ^ ((r & 7) << 4));
    }
    #pragma unroll
    for (int nt2 = 0; nt2 < 4; nt2++) {
        int r = wn * 64 + nt2 * 16 + br;
        #pragma unroll
        for (int ks = 0; ks < 4; ks++)
            bOff[nt2][ks] = (uint32_t)BOFF + (uint32_t)(r << 7) + (uint32_t)(((ks << 5) + bkb) ^ ((r & 7) << 4));
    }

    const int NC = K >> 6;
    #pragma unroll
    for (int s = 0; s < 2; s++) {
        uint32_t stB = sb + s * STAGE;
        int k0 = s << 6;
        #pragma unroll
        for (int it = 0; it < 4; it++) {
            cpa16(stB + dstOff[it], Ahb + k0 + gOffA[it]);
            cpa16(stB + BOFF + dstOff[it], Bpb + k0 + gOffB[it]);
        }
        asm volatile("cp.async.commit_group;" ::: "memory");
    }

    for (int c = 0; c < NC; c++) {
        asm volatile("cp.async.wait_group 1;" ::: "memory");
        __syncthreads();
        int pf = c + NSTAGE - 1;
        if (pf < NC) {
            uint32_t stB = sb + (pf % NSTAGE) * STAGE;
            int k0 = pf << 6;
            #pragma unroll
            for (int it = 0; it < 4; it++) {
                cpa16(stB + dstOff[it], Ahb + k0 + gOffA[it]);
                cpa16(stB + BOFF + dstOff[it], Bpb + k0 + gOffB[it]);
            }
        }
        asm volatile("cp.async.commit_group;" ::: "memory");

        uint32_t st = sb + (c % NSTAGE) * STAGE;
        #pragma unroll
        for (int ks = 0; ks < 4; ks++) {
            uint32_t a_h[2][4];
            #pragma unroll
            for (int mt = 0; mt < 2; mt++) ldmx4(a_h[mt], st + aOff[mt][ks]);
            #pragma unroll
            for (int nt2 = 0; nt2 < 4; nt2++) {
                uint32_t b_f[4];
                ldmx4(b_f, st + bOff[nt2][ks]);
                #pragma unroll
                for (int mt = 0; mt < 2; mt++) {
                    mma16816(acc[mt][nt2 * 2],     a_h[mt], b_f);
                    mma16816(acc[mt][nt2 * 2 + 1], a_h[mt], b_f + 2);
                }
            }
        }
    }

    const int rB = lane >> 2;
    const int cB = (lane & 3) * 2;

    if (EPI == 0) {
        u16* P = o1 + sOut * bz;
        float* part = outF + (size_t)bz * N_PIX * 64;
        #pragma unroll
        for (int mt = 0; mt < 2; mt++)
            #pragma unroll
            for (int h = 0; h < 2; h++) {
                int rowG = m0 + wm * 32 + mt * 16 + rB + h * 8;
                float rs = 0.f;
                #pragma unroll
                for (int nt = 0; nt < 8; nt++) {
                    int colG = n0 + wn * 64 + nt * 8 + cB;
                    float e0 = __expf(acc[mt][nt][h * 2]     * alpha);
                    float e1 = __expf(acc[mt][nt][h * 2 + 1] * alpha);
                    rs += e0 + e1;
                    *(uint32_t*)(P + (size_t)rowG * ldc + colG) = pk(hbits(e0), hbits(e1));
                }
                rs += __shfl_xor_sync(0xFFFFFFFFu, rs, 1);
                rs += __shfl_xor_sync(0xFFFFFFFFu, rs, 2);
                if ((lane & 3) == 0)
                    part[(size_t)rowG * 64 + blockIdx.x * 2 + wn] = rs;
            }
    } else if (EPI == 1) {
        u16* O = o1 + sOut * bz;
        const float* rsum = outF + (size_t)bz * N_PIX;
        #pragma unroll
        for (int mt = 0; mt < 2; mt++)
            #pragma unroll
            for (int h = 0; h < 2; h++) {
                int rowG = m0 + wm * 32 + mt * 16 + rB + h * 8;
                float inv = rsum[rowG];
                #pragma unroll
                for (int nt = 0; nt < 8; nt++) {
                    int colG = n0 + wn * 64 + nt * 8 + cB;
                    *(uint32_t*)(O + (size_t)rowG * ldc + colG) =
                        pk(hbits(acc[mt][nt][h * 2] * inv), hbits(acc[mt][nt][h * 2 + 1] * inv));
                }
            }
    } else if (EPI == 3) {
        float* Ob = outF + sOut * bz;
        const float* Rb = resid + sOut * bz;
        #pragma unroll
        for (int mt = 0; mt < 2; mt++)
            #pragma unroll
            for (int nt = 0; nt < 8; nt++)
                #pragma unroll
                for (int h = 0; h < 2; h++) {
                    int rowG = m0 + wm * 32 + mt * 16 + rB + h * 8;
                    int colG = n0 + wn * 64 + nt * 8 + cB;
                    float bv = bias[rowG];
                    size_t di = (size_t)rowG * ldc + colG;
                    float2 rv = *(const float2*)(Rb + di);
                    float2 v = make_float2(acc[mt][nt][h * 2] + bv + rv.x,
                                           acc[mt][nt][h * 2 + 1] + bv + rv.y);
                    *(float2*)(Ob + di) = v;
                }
    } else {  // EPI 2: qkv
        int sect = m0 >> 8;
        int msub = m0 & 255;
        if (sect == 2) {   // v: plain store [c][4096] + bias
            u16* V = o3 + (size_t)1048576 * bz;
            #pragma unroll
            for (int mt = 0; mt < 2; mt++)
                #pragma unroll
                for (int nt = 0; nt < 8; nt++)
                    #pragma unroll
                    for (int h = 0; h < 2; h++) {
                        int rowL = wm * 32 + mt * 16 + rB + h * 8;
                        float bv = bias[m0 + rowL];
                        int colG = n0 + wn * 64 + nt * 8 + cB;
                        *(uint32_t*)(V + (size_t)(msub + rowL) * N_PIX + colG) =
                            pk(hbits(acc[mt][nt][h * 2] + bv), hbits(acc[mt][nt][h * 2 + 1] + bv));
                    }
        } else {           // q/k: transpose via SMEM bounce -> plain [n][256]
            u16* D = (sect ? o2 : o1) + (size_t)1048576 * bz;
            float* tsm = (float*)smem;
            __syncthreads();
            #pragma unroll
            for (int mt = 0; mt < 2; mt++)
                #pragma unroll
                for (int h = 0; h < 2; h++) {
                    int rowL = wm * 32 + mt * 16 + rB + h * 8;
                    float bv = bias[m0 + rowL];
                    #pragma unroll
                    for (int nt = 0; nt < 8; nt++) {
                        int colL = wn * 64 + nt * 8 + cB;
                        tsm[rowL * 133 + colL]     = acc[mt][nt][h * 2] + bv;
                        tsm[rowL * 133 + colL + 1] = acc[mt][nt][h * 2 + 1] + bv;
                    }
                }
            __syncthreads();
            #pragma unroll
            for (int it = 0; it < 32; it++) {
                int lin = tid + (it << 8);
                int n  = lin >> 6;
                int op = (lin & 63) << 1;
                float f0 = tsm[op * 133 + n];
                float f1 = tsm[(op + 1) * 133 + n];
                *(uint32_t*)(D + (size_t)(n0 + n) * C_CH + msub + op) = pk(hbits(f0), hbits(f1));
            }
        }
    }
}

// ---------------- launch ----------------
extern "C" void kernel_launch(void* const* d_in, const int* in_sizes, int n_in,
                              void* d_out, int out_size) {
    const float* x      = (const float*)d_in[0];
    const float* gn_w   = (const float*)d_in[1];
    const float* gn_b   = (const float*)d_in[2];
    const float* qkv_w  = (const float*)d_in[3];
    const float* qkv_b  = (const float*)d_in[4];
    const float* proj_w = (const float*)d_in[5];
    const float* proj_b = (const float*)d_in[6];
    float* out = (float*)d_out;

    u16 *w, *p, *xn, *qT, *kT, *v, *P, *O;
    float *part, *rsum;
    float2* gnp;
    cudaGetSymbolAddress((void**)&w, g_w);     cudaGetSymbolAddress((void**)&p, g_p);
    cudaGetSymbolAddress((void**)&xn, g_xn);
    cudaGetSymbolAddress((void**)&qT, g_qT);   cudaGetSymbolAddress((void**)&kT, g_kT);
    cudaGetSymbolAddress((void**)&v, g_v);     cudaGetSymbolAddress((void**)&P, g_P);
    cudaGetSymbolAddress((void**)&O, g_O);
    cudaGetSymbolAddress((void**)&part, g_part);
    cudaGetSymbolAddress((void**)&rsum, g_rsum);
    cudaGetSymbolAddress((void**)&gnp, g_gnp);

    cudaFuncSetAttribute((const void*)gemm_mma<0>, cudaFuncAttributeMaxDynamicSharedMemorySize, SMEM_A1);
    cudaFuncSetAttribute((const void*)gemm_mma<1>, cudaFuncAttributeMaxDynamicSharedMemorySize, SMEM_A1);
    cudaFuncSetAttribute((const void*)gemm_mma<2>, cudaFuncAttributeMaxDynamicSharedMemorySize, SMEM_A1);
    cudaFuncSetAttribute((const void*)gemm_mma<3>, cudaFuncAttributeMaxDynamicSharedMemorySize, SMEM_A1);

    const long long sNC  = (long long)N_PIX * C_CH;      // 1M
    const long long sATT = (long long)N_PIX * N_PIX;     // 16M

    // 0) convert weights to fp16
    conv_w<<<1024, 256>>>(qkv_w, proj_w, w, p);

    // 1) GroupNorm stats + apply -> xn^T plain fp16
    gn_stats<<<dim3(64, 8), 256>>>(x, gnp);
    gn_apply<<<dim3(64, 8), 256>>>(x, gn_w, gn_b, gnp, xn);

    // 2) QKV (plain fp16): -> q/k plain T, v plain
    gemm_mma<2><<<dim3(32, 6, B_SZ), 256, SMEM_A1>>>(
        w, 0, C_CH, xn, sNC, C_CH, C_CH, 0, 0, 1.0f,
        qkv_b, nullptr, nullptr, qT, kT, v);

    // 3) scores+exp: P~[i,j] = exp((1/16) sum_c qT[i,c] kT[j,c]) + partial sums
    gemm_mma<0><<<dim3(32, 32, B_SZ), 256, SMEM_A1>>>(
        qT, sNC, C_CH, kT, sNC, C_CH, C_CH, N_PIX, sATT, 0.0625f,
        nullptr, nullptr, part, P, nullptr, nullptr);

    // 4) rowsum reduce -> reciprocal sums
    rowsum_reduce<<<(B_SZ * N_PIX) / 8, 256>>>(part, rsum);

    // 5) AV: O[i,c] = (sum_m P~[i,m] v[c,m]) / rowsum_i -> plain store [i][c]
    gemm_mma<1><<<dim3(2, 32, B_SZ), 256, SMEM_A1>>>(
        P, sATT, N_PIX, v, sNC, N_PIX, N_PIX, C_CH, sNC, 1.0f,
        nullptr, nullptr, rsum, O, nullptr, nullptr);

    // 6) proj (plain fp16): out[o,i] = sum_c Pw[o,c] O[i,c] + pb[o] + x
    gemm_mma<3><<<dim3(32, 2, B_SZ), 256, SMEM_A1>>>(
        p, 0, C_CH, O, sNC, C_CH, C_CH, N_PIX, sNC, 1.0f,
        proj_b, x, out, nullptr, nullptr, nullptr);
}